// round 3
// baseline (speedup 1.0000x reference)
#include <cuda_runtime.h>
#include <cuda_bf16.h>
#include <cstdint>
#include <cstdio>

// Problem constants (fixed by the dataset)
#define B_  16
#define LQ_ 2048
#define S_  2048
#define D_  1024

// Scratch for out1 = A @ V : [B, LQ, D] fp32 (128 MB). __device__ global =
// allocation-guard-safe scratch.
static __device__ float g_out1[(size_t)B_ * LQ_ * D_];

__device__ __forceinline__ unsigned long long pack2(float lo, float hi) {
    unsigned long long r;
    asm("mov.b64 %0, {%1, %2};" : "=l"(r) : "f"(lo), "f"(hi));
    return r;
}

// Generic batched 128x128 tile GEMM, fp32, packed f32x2 FMA inner loop.
//   C[m,n] = scale * sum_k A(m,k) * B(k,n)
// A_KC = true : A stored [M,K] row-major (k contiguous)
// A_KC = false: A stored [K,M] row-major (m contiguous)  -> computes with A^T naturally
// B_KC = true : B stored [N,K] row-major (k contiguous)
// B_KC = false: B stored [K,N] row-major (n contiguous)
// All dims must be multiples of the tile (they are: 2048/1024, K mult of 16).
template<bool A_KC, bool B_KC>
__global__ void __launch_bounds__(256, 2) gemm128(
    const float* __restrict__ Ag, const float* __restrict__ Bg, float* __restrict__ Cg,
    int M, int N, int K, size_t sA, size_t sB, size_t sC, float scale)
{
    const float* A  = Ag + (size_t)blockIdx.z * sA;
    const float* Bp = Bg + (size_t)blockIdx.z * sB;
    float*       C  = Cg + (size_t)blockIdx.z * sC;

    const int bm  = blockIdx.y * 128;
    const int bn  = blockIdx.x * 128;
    const int tid = threadIdx.x;
    const int tm  = (tid >> 4) * 8;   // 16x16 thread grid, 8x8 micro-tile
    const int tn  = (tid & 15) * 8;

    // +4 padding: conflict-free transposed scalar stores AND keeps 16B
    // alignment for float4 row accesses (132*4 bytes = 528, mult of 16).
    __shared__ float As[16][132];
    __shared__ float Bs[16][132];

    unsigned long long acc[8][4];
    #pragma unroll
    for (int i = 0; i < 8; ++i)
        #pragma unroll
        for (int j = 0; j < 4; ++j) acc[i][j] = 0ull;

    const int KT = K >> 4;
    for (int kt = 0; kt < KT; ++kt) {
        // ---- load A tile -> As[k][m] (2048 floats, 2 float4 per thread) ----
        #pragma unroll
        for (int l = 0; l < 2; ++l) {
            int f = tid + l * 256;
            if (A_KC) {
                int row = f >> 2;                 // m within tile
                int kc  = (f & 3) << 2;           // k within tile (float4)
                float4 v4 = *reinterpret_cast<const float4*>(
                    &A[(size_t)(bm + row) * K + (kt << 4) + kc]);
                As[kc + 0][row] = v4.x; As[kc + 1][row] = v4.y;
                As[kc + 2][row] = v4.z; As[kc + 3][row] = v4.w;
            } else {
                int kk = f >> 5;                  // k within tile
                int mc = (f & 31) << 2;           // m within tile (float4)
                *reinterpret_cast<float4*>(&As[kk][mc]) =
                    *reinterpret_cast<const float4*>(
                        &A[(size_t)((kt << 4) + kk) * M + bm + mc]);
            }
        }
        // ---- load B tile -> Bs[k][n] ----
        #pragma unroll
        for (int l = 0; l < 2; ++l) {
            int f = tid + l * 256;
            if (B_KC) {
                int row = f >> 2;                 // n within tile
                int kc  = (f & 3) << 2;
                float4 v4 = *reinterpret_cast<const float4*>(
                    &Bp[(size_t)(bn + row) * K + (kt << 4) + kc]);
                Bs[kc + 0][row] = v4.x; Bs[kc + 1][row] = v4.y;
                Bs[kc + 2][row] = v4.z; Bs[kc + 3][row] = v4.w;
            } else {
                int kk = f >> 5;
                int nc = (f & 31) << 2;
                *reinterpret_cast<float4*>(&Bs[kk][nc]) =
                    *reinterpret_cast<const float4*>(
                        &Bp[(size_t)((kt << 4) + kk) * N + bn + nc]);
            }
        }
        __syncthreads();

        #pragma unroll
        for (int k = 0; k < 16; ++k) {
            float4 a0 = *reinterpret_cast<const float4*>(&As[k][tm]);
            float4 a1 = *reinterpret_cast<const float4*>(&As[k][tm + 4]);
            float4 b0 = *reinterpret_cast<const float4*>(&Bs[k][tn]);
            float4 b1 = *reinterpret_cast<const float4*>(&Bs[k][tn + 4]);
            unsigned long long bb[4];
            bb[0] = pack2(b0.x, b0.y); bb[1] = pack2(b0.z, b0.w);
            bb[2] = pack2(b1.x, b1.y); bb[3] = pack2(b1.z, b1.w);
            float av[8] = {a0.x, a0.y, a0.z, a0.w, a1.x, a1.y, a1.z, a1.w};
            #pragma unroll
            for (int i = 0; i < 8; ++i) {
                unsigned long long aa = pack2(av[i], av[i]);
                #pragma unroll
                for (int j = 0; j < 4; ++j)
                    asm("fma.rn.f32x2 %0, %1, %2, %0;"
                        : "+l"(acc[i][j]) : "l"(aa), "l"(bb[j]));
            }
        }
        __syncthreads();
    }

    union F2U { unsigned long long u; float2 f; };
    #pragma unroll
    for (int i = 0; i < 8; ++i) {
        float* crow = C + (size_t)(bm + tm + i) * N + bn + tn;
        F2U p0, p1, p2, p3;
        p0.u = acc[i][0]; p1.u = acc[i][1]; p2.u = acc[i][2]; p3.u = acc[i][3];
        float4 c0 = make_float4(p0.f.x * scale, p0.f.y * scale,
                                p1.f.x * scale, p1.f.y * scale);
        float4 c1 = make_float4(p2.f.x * scale, p2.f.y * scale,
                                p3.f.x * scale, p3.f.y * scale);
        *reinterpret_cast<float4*>(crow)     = c0;
        *reinterpret_cast<float4*>(crow + 4) = c1;
    }
}

// Masked row softmax over S=2048, in place on the attention-weights buffer.
// One block per (b, q) row; 256 threads x 8 elements.
__global__ void __launch_bounds__(256) softmax_mask_kernel(
    float* __restrict__ aw, const int* __restrict__ mask)
{
    const int row = blockIdx.x;           // b * LQ + q
    const int b   = row >> 11;            // / 2048
    float*       rp = aw   + (size_t)row * S_;
    const int*   mp = mask + (size_t)b   * S_;
    const int    t  = threadIdx.x;
    const float  NEG_INF = __int_as_float(0xff800000);

    float v[8]; int mk[8];
    float mx = NEG_INF;
    #pragma unroll
    for (int i = 0; i < 8; ++i) {
        int j = t + (i << 8);
        mk[i] = mp[j];
        float s = rp[j];
        v[i] = mk[i] ? s : NEG_INF;
        mx = fmaxf(mx, v[i]);
    }

    __shared__ float smax[8];
    __shared__ float ssum[8];
    #pragma unroll
    for (int off = 16; off > 0; off >>= 1)
        mx = fmaxf(mx, __shfl_xor_sync(0xffffffffu, mx, off));
    if ((t & 31) == 0) smax[t >> 5] = mx;
    __syncthreads();
    float rmax = smax[0];
    #pragma unroll
    for (int i = 1; i < 8; ++i) rmax = fmaxf(rmax, smax[i]);

    float e[8];
    float sum = 0.f;
    #pragma unroll
    for (int i = 0; i < 8; ++i) {
        e[i] = mk[i] ? __expf(v[i] - rmax) : 0.f;
        sum += e[i];
    }
    #pragma unroll
    for (int off = 16; off > 0; off >>= 1)
        sum += __shfl_xor_sync(0xffffffffu, sum, off);
    if ((t & 31) == 0) ssum[t >> 5] = sum;
    __syncthreads();
    float rsum = 0.f;
    #pragma unroll
    for (int i = 0; i < 8; ++i) rsum += ssum[i];
    const float inv = 1.f / rsum;

    #pragma unroll
    for (int i = 0; i < 8; ++i)
        rp[t + (i << 8)] = e[i] * inv;
}

extern "C" void kernel_launch(void* const* d_in, const int* in_sizes, int n_in,
                              void* d_out, int out_size)
{
    const float* q    = (const float*)d_in[0];   // [B, LQ, D]
    const float* kk   = (const float*)d_in[1];   // [B, S, D]
    const float* v    = (const float*)d_in[2];   // [B, S, D]
    const int*   mask = (const int*)  d_in[3];   // [B, 1, S]

    float* out = (float*)d_out;                  // output [B, S, D] first
    float* aw  = out + (size_t)B_ * S_ * D_;     // then attention_weights [B, LQ, S]

    void* p = nullptr;
    cudaGetSymbolAddress(&p, g_out1);
    float* out1 = (float*)p;

    dim3 blk(256);

    // 1) scores = Q @ K^T / sqrt(D)  -> aw (raw, mask applied in softmax)
    //    A = Q [LQ, D] (k-contig), B = K [S, D] (k-contig)
    gemm128<true, true><<<dim3(S_ / 128, LQ_ / 128, B_), blk>>>(
        q, kk, aw, LQ_, S_, D_,
        (size_t)LQ_ * D_, (size_t)S_ * D_, (size_t)LQ_ * S_, 0.03125f);

    // 2) masked softmax in place on aw
    softmax_mask_kernel<<<B_ * LQ_, blk>>>(aw, mask);

    // 3) out1 = A @ V : A [LQ, S] (k-contig), V [S, D] (n-contig)
    gemm128<true, false><<<dim3(D_ / 128, LQ_ / 128, B_), blk>>>(
        aw, v, out1, LQ_, D_, S_,
        (size_t)LQ_ * S_, (size_t)S_ * D_, (size_t)LQ_ * D_, 1.0f);

    // 4) output = A^T @ out1 : A stored [LQ, S] read as [K=LQ, M=S] (m-contig),
    //    out1 [LQ, D] (n-contig)
    gemm128<false, false><<<dim3(D_ / 128, S_ / 128, B_), blk>>>(
        aw, out1, out, S_, D_, LQ_,
        (size_t)LQ_ * S_, (size_t)LQ_ * D_, (size_t)S_ * D_, 1.0f);
}

// round 4
// speedup vs baseline: 1.0013x; 1.0013x over previous
#include <cuda_runtime.h>
#include <cuda_bf16.h>
#include <cstdint>
#include <cstdio>

// Problem constants (fixed by the dataset)
#define B_  16
#define LQ_ 2048
#define S_  2048
#define D_  1024

// Scratch for out1 = A @ V : [B, LQ, D] fp32 (128 MB). __device__ global =
// allocation-guard-safe scratch.
static __device__ float g_out1[(size_t)B_ * LQ_ * D_];

__device__ __forceinline__ unsigned long long pack2(float lo, float hi) {
    unsigned long long r;
    asm("mov.b64 %0, {%1, %2};" : "=l"(r) : "f"(lo), "f"(hi));
    return r;
}

// Generic batched 128x128 tile GEMM, fp32, packed f32x2 FMA inner loop.
//   C[m,n] = scale * sum_k A(m,k) * B(k,n)
// A_KC = true : A stored [M,K] row-major (k contiguous)
// A_KC = false: A stored [K,M] row-major (m contiguous)  -> computes with A^T naturally
// B_KC = true : B stored [N,K] row-major (k contiguous)
// B_KC = false: B stored [K,N] row-major (n contiguous)
// All dims must be multiples of the tile (they are: 2048/1024, K mult of 16).
template<bool A_KC, bool B_KC>
__global__ void __launch_bounds__(256, 2) gemm128(
    const float* __restrict__ Ag, const float* __restrict__ Bg, float* __restrict__ Cg,
    int M, int N, int K, size_t sA, size_t sB, size_t sC, float scale)
{
    const float* A  = Ag + (size_t)blockIdx.z * sA;
    const float* Bp = Bg + (size_t)blockIdx.z * sB;
    float*       C  = Cg + (size_t)blockIdx.z * sC;

    const int bm  = blockIdx.y * 128;
    const int bn  = blockIdx.x * 128;
    const int tid = threadIdx.x;
    const int tm  = (tid >> 4) * 8;   // 16x16 thread grid, 8x8 micro-tile
    const int tn  = (tid & 15) * 8;

    // +4 padding: conflict-free transposed scalar stores AND keeps 16B
    // alignment for float4 row accesses (132*4 bytes = 528, mult of 16).
    __shared__ float As[16][132];
    __shared__ float Bs[16][132];

    unsigned long long acc[8][4];
    #pragma unroll
    for (int i = 0; i < 8; ++i)
        #pragma unroll
        for (int j = 0; j < 4; ++j) acc[i][j] = 0ull;

    const int KT = K >> 4;
    for (int kt = 0; kt < KT; ++kt) {
        // ---- load A tile -> As[k][m] (2048 floats, 2 float4 per thread) ----
        #pragma unroll
        for (int l = 0; l < 2; ++l) {
            int f = tid + l * 256;
            if (A_KC) {
                int row = f >> 2;                 // m within tile
                int kc  = (f & 3) << 2;           // k within tile (float4)
                float4 v4 = *reinterpret_cast<const float4*>(
                    &A[(size_t)(bm + row) * K + (kt << 4) + kc]);
                As[kc + 0][row] = v4.x; As[kc + 1][row] = v4.y;
                As[kc + 2][row] = v4.z; As[kc + 3][row] = v4.w;
            } else {
                int kk = f >> 5;                  // k within tile
                int mc = (f & 31) << 2;           // m within tile (float4)
                *reinterpret_cast<float4*>(&As[kk][mc]) =
                    *reinterpret_cast<const float4*>(
                        &A[(size_t)((kt << 4) + kk) * M + bm + mc]);
            }
        }
        // ---- load B tile -> Bs[k][n] ----
        #pragma unroll
        for (int l = 0; l < 2; ++l) {
            int f = tid + l * 256;
            if (B_KC) {
                int row = f >> 2;                 // n within tile
                int kc  = (f & 3) << 2;
                float4 v4 = *reinterpret_cast<const float4*>(
                    &Bp[(size_t)(bn + row) * K + (kt << 4) + kc]);
                Bs[kc + 0][row] = v4.x; Bs[kc + 1][row] = v4.y;
                Bs[kc + 2][row] = v4.z; Bs[kc + 3][row] = v4.w;
            } else {
                int kk = f >> 5;
                int nc = (f & 31) << 2;
                *reinterpret_cast<float4*>(&Bs[kk][nc]) =
                    *reinterpret_cast<const float4*>(
                        &Bp[(size_t)((kt << 4) + kk) * N + bn + nc]);
            }
        }
        __syncthreads();

        #pragma unroll
        for (int k = 0; k < 16; ++k) {
            float4 a0 = *reinterpret_cast<const float4*>(&As[k][tm]);
            float4 a1 = *reinterpret_cast<const float4*>(&As[k][tm + 4]);
            float4 b0 = *reinterpret_cast<const float4*>(&Bs[k][tn]);
            float4 b1 = *reinterpret_cast<const float4*>(&Bs[k][tn + 4]);
            unsigned long long bb[4];
            bb[0] = pack2(b0.x, b0.y); bb[1] = pack2(b0.z, b0.w);
            bb[2] = pack2(b1.x, b1.y); bb[3] = pack2(b1.z, b1.w);
            float av[8] = {a0.x, a0.y, a0.z, a0.w, a1.x, a1.y, a1.z, a1.w};
            #pragma unroll
            for (int i = 0; i < 8; ++i) {
                unsigned long long aa = pack2(av[i], av[i]);
                #pragma unroll
                for (int j = 0; j < 4; ++j)
                    asm("fma.rn.f32x2 %0, %1, %2, %0;"
                        : "+l"(acc[i][j]) : "l"(aa), "l"(bb[j]));
            }
        }
        __syncthreads();
    }

    union F2U { unsigned long long u; float2 f; };
    #pragma unroll
    for (int i = 0; i < 8; ++i) {
        float* crow = C + (size_t)(bm + tm + i) * N + bn + tn;
        F2U p0, p1, p2, p3;
        p0.u = acc[i][0]; p1.u = acc[i][1]; p2.u = acc[i][2]; p3.u = acc[i][3];
        float4 c0 = make_float4(p0.f.x * scale, p0.f.y * scale,
                                p1.f.x * scale, p1.f.y * scale);
        float4 c1 = make_float4(p2.f.x * scale, p2.f.y * scale,
                                p3.f.x * scale, p3.f.y * scale);
        *reinterpret_cast<float4*>(crow)     = c0;
        *reinterpret_cast<float4*>(crow + 4) = c1;
    }
}

// Masked row softmax over S=2048, in place on the attention-weights buffer.
// One block per (b, q) row; 256 threads x 8 elements.
__global__ void __launch_bounds__(256) softmax_mask_kernel(
    float* __restrict__ aw, const int* __restrict__ mask)
{
    const int row = blockIdx.x;           // b * LQ + q
    const int b   = row >> 11;            // / 2048
    float*       rp = aw   + (size_t)row * S_;
    const int*   mp = mask + (size_t)b   * S_;
    const int    t  = threadIdx.x;
    const float  NEG_INF = __int_as_float(0xff800000);

    float v[8]; int mk[8];
    float mx = NEG_INF;
    #pragma unroll
    for (int i = 0; i < 8; ++i) {
        int j = t + (i << 8);
        mk[i] = mp[j];
        float s = rp[j];
        v[i] = mk[i] ? s : NEG_INF;
        mx = fmaxf(mx, v[i]);
    }

    __shared__ float smax[8];
    __shared__ float ssum[8];
    #pragma unroll
    for (int off = 16; off > 0; off >>= 1)
        mx = fmaxf(mx, __shfl_xor_sync(0xffffffffu, mx, off));
    if ((t & 31) == 0) smax[t >> 5] = mx;
    __syncthreads();
    float rmax = smax[0];
    #pragma unroll
    for (int i = 1; i < 8; ++i) rmax = fmaxf(rmax, smax[i]);

    float e[8];
    float sum = 0.f;
    #pragma unroll
    for (int i = 0; i < 8; ++i) {
        e[i] = mk[i] ? __expf(v[i] - rmax) : 0.f;
        sum += e[i];
    }
    #pragma unroll
    for (int off = 16; off > 0; off >>= 1)
        sum += __shfl_xor_sync(0xffffffffu, sum, off);
    if ((t & 31) == 0) ssum[t >> 5] = sum;
    __syncthreads();
    float rsum = 0.f;
    #pragma unroll
    for (int i = 0; i < 8; ++i) rsum += ssum[i];
    const float inv = 1.f / rsum;

    #pragma unroll
    for (int i = 0; i < 8; ++i)
        rp[t + (i << 8)] = e[i] * inv;
}

extern "C" void kernel_launch(void* const* d_in, const int* in_sizes, int n_in,
                              void* d_out, int out_size)
{
    const float* q    = (const float*)d_in[0];   // [B, LQ, D]
    const float* kk   = (const float*)d_in[1];   // [B, S, D]
    const float* v    = (const float*)d_in[2];   // [B, S, D]
    const int*   mask = (const int*)  d_in[3];   // [B, 1, S]

    float* out = (float*)d_out;                  // output [B, S, D] first
    float* aw  = out + (size_t)B_ * S_ * D_;     // then attention_weights [B, LQ, S]

    void* p = nullptr;
    cudaGetSymbolAddress(&p, g_out1);
    float* out1 = (float*)p;

    dim3 blk(256);

    // 1) scores = Q @ K^T / sqrt(D)  -> aw (raw, mask applied in softmax)
    //    A = Q [LQ, D] (k-contig), B = K [S, D] (k-contig)
    gemm128<true, true><<<dim3(S_ / 128, LQ_ / 128, B_), blk>>>(
        q, kk, aw, LQ_, S_, D_,
        (size_t)LQ_ * D_, (size_t)S_ * D_, (size_t)LQ_ * S_, 0.03125f);

    // 2) masked softmax in place on aw
    softmax_mask_kernel<<<B_ * LQ_, blk>>>(aw, mask);

    // 3) out1 = A @ V : A [LQ, S] (k-contig), V [S, D] (n-contig)
    gemm128<true, false><<<dim3(D_ / 128, LQ_ / 128, B_), blk>>>(
        aw, v, out1, LQ_, D_, S_,
        (size_t)LQ_ * S_, (size_t)S_ * D_, (size_t)LQ_ * D_, 1.0f);

    // 4) output = A^T @ out1 : A stored [LQ, S] read as [K=LQ, M=S] (m-contig),
    //    out1 [LQ, D] (n-contig)
    gemm128<false, false><<<dim3(D_ / 128, S_ / 128, B_), blk>>>(
        aw, out1, out, S_, D_, LQ_,
        (size_t)LQ_ * S_, (size_t)LQ_ * D_, (size_t)S_ * D_, 1.0f);
}

// round 7
// speedup vs baseline: 1.8853x; 1.8829x over previous
#include <cuda_runtime.h>
#include <cuda_bf16.h>
#include <cstdint>

#define B_  16
#define LQ_ 2048
#define S_  2048
#define D_  1024
#define K3QK 3072    // 3*D
#define K3A  6144    // 3*S == 3*LQ

// ------------- scratch (__device__ globals = allocation-guard-safe) -------------
static __device__ __nv_bfloat16 g_qs  [(size_t)B_ * LQ_ * K3QK];  // Q split  A-role [h|h|l]
static __device__ __nv_bfloat16 g_ks  [(size_t)B_ * S_  * K3QK];  // K split  B-role [h|l|h]
static __device__ __nv_bfloat16 g_vts [(size_t)B_ * D_  * K3A];   // V^T split B-role
static __device__ __nv_bfloat16 g_aws [(size_t)B_ * LQ_ * K3A];   // aw split  A-role
static __device__ __nv_bfloat16 g_awts[(size_t)B_ * S_  * K3A];   // aw^T split A-role
static __device__ __nv_bfloat16 g_o1ts[(size_t)B_ * D_  * K3A];   // out1^T split B-role

// ------------- PTX helpers (sm_100 baseline ISA only: cp.async/ldmatrix/mma.sync) ----
__device__ __forceinline__ uint32_t smem_u32(const void* p) {
    uint32_t a;
    asm("{ .reg .u64 t; cvta.to.shared.u64 t, %1; cvt.u32.u64 %0, t; }" : "=r"(a) : "l"(p));
    return a;
}
#define CP_ASYNC16(dst, src) \
    asm volatile("cp.async.cg.shared.global [%0], [%1], 16;" :: "r"(dst), "l"(src) : "memory")
#define CP_COMMIT() asm volatile("cp.async.commit_group;" ::: "memory")
#define CP_WAIT1()  asm volatile("cp.async.wait_group 1;" ::: "memory")
#define CP_WAIT0()  asm volatile("cp.async.wait_group 0;" ::: "memory")

__device__ __forceinline__ void ldsm_x4(uint32_t& r0, uint32_t& r1, uint32_t& r2,
                                        uint32_t& r3, uint32_t addr) {
    asm volatile("ldmatrix.sync.aligned.m8n8.x4.shared.b16 {%0,%1,%2,%3}, [%4];"
                 : "=r"(r0), "=r"(r1), "=r"(r2), "=r"(r3) : "r"(addr));
}
__device__ __forceinline__ void mma_bf16(float* c, uint32_t a0, uint32_t a1,
                                         uint32_t a2, uint32_t a3,
                                         uint32_t b0, uint32_t b1) {
    asm volatile(
        "mma.sync.aligned.m16n8k16.row.col.f32.bf16.bf16.f32 "
        "{%0,%1,%2,%3}, {%4,%5,%6,%7}, {%8,%9}, {%0,%1,%2,%3};"
        : "+f"(c[0]), "+f"(c[1]), "+f"(c[2]), "+f"(c[3])
        : "r"(a0), "r"(a1), "r"(a2), "r"(a3), "r"(b0), "r"(b1));
}

static constexpr int SMEM_SZ = 69632;   // 1KB align pad + max(64KB operands, 66KB slab)

// ------------- mma.sync GEMM: C[M,N] = scale * A[M,K3] @ B[N,K3]^T -------------
// CTA tile 128x128, 8 warps (2m x 4n), warp tile 64x32, K chunks of 64 bf16 with
// SW128 xor-swizzle; cp.async double buffer.
// EPI=0: fp32 row-major C (ldc, scale). EPI=1: bf16 [h|l|h] transposed into Tg
//        with row pitch K3A (B-role split of C^T).
template<int EPI>
__global__ void __launch_bounds__(256) gemm_mma(
    const __nv_bfloat16* __restrict__ Ag,
    const __nv_bfloat16* __restrict__ Bg,
    float* __restrict__ Cg, __nv_bfloat16* __restrict__ Tg,
    int K3, int ldc, size_t sA, size_t sB, size_t sOut, float scale)
{
    extern __shared__ char dsm[];
    const uint32_t raw  = smem_u32(dsm);
    const uint32_t base = (raw + 1023u) & ~1023u;
    char* sm = dsm + (base - raw);

    const int tid  = threadIdx.x;
    const int wid  = tid >> 5;
    const int lane = tid & 31;
    const int bm   = blockIdx.y * 128;
    const int bn   = blockIdx.x * 128;
    const __nv_bfloat16* A  = Ag + blockIdx.z * sA;
    const __nv_bfloat16* Bp = Bg + blockIdx.z * sB;

    const uint32_t abuf = base;            // 2 x 16KB
    const uint32_t bbuf = base + 32768;    // 2 x 16KB

    const int wm = (wid & 1) * 64;         // warp m-offset in tile
    const int wn = (wid >> 1) * 32;        // warp n-offset in tile

    float acc[4][4][4];
    #pragma unroll
    for (int i = 0; i < 4; ++i)
        #pragma unroll
        for (int j = 0; j < 4; ++j)
            #pragma unroll
            for (int r = 0; r < 4; ++r) acc[i][j][r] = 0.f;

    // per-thread load slots: 4 chunks of A, 4 of B per 64-K step
    const int lr  = tid >> 1;                    // 0..127: row
    const int lc0 = (tid & 1) << 2;              // chunk 0..3 or 4..7 base

    const int NT = K3 >> 6;

    auto load_chunk = [&](int kt, int buf) {
        const int kc = kt << 6;
        const uint32_t ab = abuf + buf * 16384;
        const uint32_t bb = bbuf + buf * 16384;
        const __nv_bfloat16* arow = A  + (size_t)(bm + lr) * K3 + kc;
        const __nv_bfloat16* brow = Bp + (size_t)(bn + lr) * K3 + kc;
        #pragma unroll
        for (int c = 0; c < 4; ++c) {
            int c16 = lc0 + c;
            uint32_t sw = (uint32_t)((c16 ^ (lr & 7)) << 4);
            CP_ASYNC16(ab + (uint32_t)(lr << 7) + sw, arow + (c16 << 3));
            CP_ASYNC16(bb + (uint32_t)(lr << 7) + sw, brow + (c16 << 3));
        }
        CP_COMMIT();
    };

    load_chunk(0, 0);

    for (int kt = 0; kt < NT; ++kt) {
        const int buf = kt & 1;
        if (kt + 1 < NT) { load_chunk(kt + 1, buf ^ 1); CP_WAIT1(); }
        else             { CP_WAIT0(); }
        __syncthreads();

        const uint32_t ab = abuf + buf * 16384;
        const uint32_t bb = bbuf + buf * 16384;

        #pragma unroll
        for (int ks = 0; ks < 4; ++ks) {
            // A fragments: 4 m16 tiles
            uint32_t Af[4][4];
            #pragma unroll
            for (int mt = 0; mt < 4; ++mt) {
                int t4  = lane >> 3;
                int row = wm + mt * 16 + ((t4 & 1) << 3) + (lane & 7);
                int c16 = ks * 2 + (t4 >> 1);
                uint32_t addr = ab + (uint32_t)(row << 7)
                              + (uint32_t)(((c16 ^ (row & 7)) << 4));
                ldsm_x4(Af[mt][0], Af[mt][1], Af[mt][2], Af[mt][3], addr);
            }
            // B fragments: 2 n16 groups, regs = [b0 n0-7][b1 n0-7][b0 n8-15][b1 n8-15]
            uint32_t Bf[2][4];
            #pragma unroll
            for (int gt = 0; gt < 2; ++gt) {
                int t4  = lane >> 3;
                int row = wn + gt * 16 + ((t4 >> 1) << 3) + (lane & 7);
                int c16 = ks * 2 + (t4 & 1);
                uint32_t addr = bb + (uint32_t)(row << 7)
                              + (uint32_t)(((c16 ^ (row & 7)) << 4));
                ldsm_x4(Bf[gt][0], Bf[gt][1], Bf[gt][2], Bf[gt][3], addr);
            }
            #pragma unroll
            for (int mt = 0; mt < 4; ++mt)
                #pragma unroll
                for (int ng = 0; ng < 4; ++ng) {
                    const uint32_t* bg = Bf[ng >> 1];
                    mma_bf16(acc[mt][ng],
                             Af[mt][0], Af[mt][1], Af[mt][2], Af[mt][3],
                             bg[(ng & 1) * 2], bg[(ng & 1) * 2 + 1]);
                }
        }
        __syncthreads();
    }

    // ---------------- epilogue (operand smem reused as slab) ----------------
    const int qr = lane >> 2;          // 0..7
    const int qc = (lane & 3) << 1;    // 0,2,4,6

    if (EPI == 0) {
        float* slab = reinterpret_cast<float*>(sm);   // [m][n] pitch 132
        #pragma unroll
        for (int mt = 0; mt < 4; ++mt)
            #pragma unroll
            for (int ng = 0; ng < 4; ++ng) {
                int m = wm + mt * 16 + qr;
                int n = wn + ng * 8 + qc;
                float* p0 = slab + (size_t)m * 132 + n;
                p0[0]   = acc[mt][ng][0] * scale;
                p0[1]   = acc[mt][ng][1] * scale;
                float* p1 = p0 + 8 * 132;
                p1[0]   = acc[mt][ng][2] * scale;
                p1[1]   = acc[mt][ng][3] * scale;
            }
        __syncthreads();
        float* C = Cg + blockIdx.z * sOut;
        #pragma unroll
        for (int it = 0; it < 16; ++it) {
            int idx = tid + (it << 8);
            int r = idx >> 5, c = (idx & 31) << 2;
            float4 v = *reinterpret_cast<float4*>(slab + (size_t)r * 132 + c);
            *reinterpret_cast<float4*>(C + (size_t)(bm + r) * ldc + bn + c) = v;
        }
    } else {
        float* slab = reinterpret_cast<float*>(sm);   // [n][m] pitch 132 (transposed)
        #pragma unroll
        for (int mt = 0; mt < 4; ++mt)
            #pragma unroll
            for (int ng = 0; ng < 4; ++ng) {
                int m = wm + mt * 16 + qr;
                int n = wn + ng * 8 + qc;
                slab[(size_t)n * 132 + m]           = acc[mt][ng][0];
                slab[(size_t)(n + 1) * 132 + m]     = acc[mt][ng][1];
                slab[(size_t)n * 132 + m + 8]       = acc[mt][ng][2];
                slab[(size_t)(n + 1) * 132 + m + 8] = acc[mt][ng][3];
            }
        __syncthreads();
        __nv_bfloat16* T = Tg + blockIdx.z * sOut;
        #pragma unroll
        for (int it = 0; it < 16; ++it) {
            int idx = tid + (it << 8);          // 4096 (n, m-chunk4) pairs
            int n = idx >> 5, mc = (idx & 31) << 2;
            float4 v = *reinterpret_cast<float4*>(slab + (size_t)n * 132 + mc);
            float xs[4] = {v.x, v.y, v.z, v.w};
            __align__(8) __nv_bfloat16 h[4], l[4];
            #pragma unroll
            for (int i = 0; i < 4; ++i) {
                h[i] = __float2bfloat16(xs[i]);
                l[i] = __float2bfloat16(xs[i] - __bfloat162float(h[i]));
            }
            __nv_bfloat16* dst = T + (size_t)(bn + n) * K3A + bm + mc;
            *reinterpret_cast<uint2*>(dst)            = *reinterpret_cast<uint2*>(h);
            *reinterpret_cast<uint2*>(dst + LQ_)      = *reinterpret_cast<uint2*>(l);
            *reinterpret_cast<uint2*>(dst + 2 * LQ_)  = *reinterpret_cast<uint2*>(h);
        }
    }
}

// ------------- fp32 -> bf16 hi/lo split, row-wise (no transpose) -------------
// ROLE 0: [h|h|l] (A-role).  ROLE 1: [h|l|h] (B-role).  Row pitch 3*Dn.
template<int ROLE>
__global__ void __launch_bounds__(256) split_rows(
    const float* __restrict__ in, __nv_bfloat16* __restrict__ out, int Dn)
{
    size_t idx = (size_t)blockIdx.x * 256 + threadIdx.x;     // one float4
    size_t row = idx / (size_t)(Dn >> 2);
    int    c   = (int)(idx % (size_t)(Dn >> 2)) << 2;
    float4 v = *reinterpret_cast<const float4*>(in + row * Dn + c);
    float xs[4] = {v.x, v.y, v.z, v.w};
    __align__(8) __nv_bfloat16 h[4], l[4];
    #pragma unroll
    for (int i = 0; i < 4; ++i) {
        h[i] = __float2bfloat16(xs[i]);
        l[i] = __float2bfloat16(xs[i] - __bfloat162float(h[i]));
    }
    __nv_bfloat16* o = out + row * (size_t)(3 * Dn) + c;
    *reinterpret_cast<uint2*>(o)                          = *reinterpret_cast<uint2*>(h);
    *reinterpret_cast<uint2*>(o + (ROLE ? 2 * Dn : Dn))   = *reinterpret_cast<uint2*>(h);
    *reinterpret_cast<uint2*>(o + (ROLE ? Dn : 2 * Dn))   = *reinterpret_cast<uint2*>(l);
}

// ------------- transpose + split: in [B][R][Cd] fp32 -> out [B][Cd][3R] bf16 -------------
template<int ROLE>
__global__ void __launch_bounds__(256) tsplit(
    const float* __restrict__ in, __nv_bfloat16* __restrict__ out, int R, int Cd)
{
    __shared__ float tile[32][33];
    const int r0 = blockIdx.x * 32, c0 = blockIdx.y * 32;
    const float* ip = in + (size_t)blockIdx.z * R * Cd;
    __nv_bfloat16* op = out + (size_t)blockIdx.z * Cd * 3 * R;
    const int tx = threadIdx.x & 31, ty = threadIdx.x >> 5;
    #pragma unroll
    for (int j = 0; j < 4; ++j)
        tile[ty + j * 8][tx] = ip[(size_t)(r0 + ty + j * 8) * Cd + c0 + tx];
    __syncthreads();
    #pragma unroll
    for (int j = 0; j < 4; ++j) {
        int cc = ty + j * 8;
        float x = tile[tx][cc];
        __nv_bfloat16 h = __float2bfloat16(x);
        __nv_bfloat16 l = __float2bfloat16(x - __bfloat162float(h));
        __nv_bfloat16* o = op + (size_t)(c0 + cc) * 3 * R + r0 + tx;
        o[0]                  = h;
        o[ROLE ? 2 * R : R]   = h;
        o[ROLE ? R : 2 * R]   = l;
    }
}

// ------------- masked softmax + A-role split of aw -------------
__global__ void __launch_bounds__(256) softmax_mask_split(
    float* __restrict__ aw, const int* __restrict__ mask, __nv_bfloat16* __restrict__ aws)
{
    const int row = blockIdx.x;
    const int b   = row >> 11;
    float*         rp = aw   + (size_t)row * S_;
    __nv_bfloat16* ap = aws  + (size_t)row * K3A;
    const int*     mp = mask + (size_t)b   * S_;
    const int t = threadIdx.x;
    const float NEG_INF = __int_as_float(0xff800000);

    float v[8]; int mk[8];
    float mx = NEG_INF;
    #pragma unroll
    for (int i = 0; i < 8; ++i) {
        int j = t + (i << 8);
        mk[i] = mp[j];
        float s = rp[j];
        v[i] = mk[i] ? s : NEG_INF;
        mx = fmaxf(mx, v[i]);
    }
    __shared__ float smax[8], ssum[8];
    #pragma unroll
    for (int off = 16; off > 0; off >>= 1)
        mx = fmaxf(mx, __shfl_xor_sync(0xffffffffu, mx, off));
    if ((t & 31) == 0) smax[t >> 5] = mx;
    __syncthreads();
    float rmax = smax[0];
    #pragma unroll
    for (int i = 1; i < 8; ++i) rmax = fmaxf(rmax, smax[i]);

    float e[8], sum = 0.f;
    #pragma unroll
    for (int i = 0; i < 8; ++i) {
        e[i] = mk[i] ? __expf(v[i] - rmax) : 0.f;
        sum += e[i];
    }
    #pragma unroll
    for (int off = 16; off > 0; off >>= 1)
        sum += __shfl_xor_sync(0xffffffffu, sum, off);
    if ((t & 31) == 0) ssum[t >> 5] = sum;
    __syncthreads();
    float rsum = 0.f;
    #pragma unroll
    for (int i = 0; i < 8; ++i) rsum += ssum[i];
    const float inv = 1.f / rsum;

    #pragma unroll
    for (int i = 0; i < 8; ++i) {
        int j = t + (i << 8);
        float p = e[i] * inv;
        rp[j] = p;
        __nv_bfloat16 h = __float2bfloat16(p);
        __nv_bfloat16 l = __float2bfloat16(p - __bfloat162float(h));
        ap[j]           = h;      // A-role [h | h | l]
        ap[S_ + j]      = h;
        ap[2 * S_ + j]  = l;
    }
}

extern "C" void kernel_launch(void* const* d_in, const int* in_sizes, int n_in,
                              void* d_out, int out_size)
{
    const float* q    = (const float*)d_in[0];
    const float* kk   = (const float*)d_in[1];
    const float* v    = (const float*)d_in[2];
    const int*   mask = (const int*)  d_in[3];

    float* out = (float*)d_out;                       // output [B,S,D]
    float* aw  = out + (size_t)B_ * S_ * D_;          // attention_weights [B,LQ,S]

    void* p;
    cudaGetSymbolAddress(&p, g_qs);   __nv_bfloat16* qs   = (__nv_bfloat16*)p;
    cudaGetSymbolAddress(&p, g_ks);   __nv_bfloat16* ks   = (__nv_bfloat16*)p;
    cudaGetSymbolAddress(&p, g_vts);  __nv_bfloat16* vts  = (__nv_bfloat16*)p;
    cudaGetSymbolAddress(&p, g_aws);  __nv_bfloat16* aws  = (__nv_bfloat16*)p;
    cudaGetSymbolAddress(&p, g_awts); __nv_bfloat16* awts = (__nv_bfloat16*)p;
    cudaGetSymbolAddress(&p, g_o1ts); __nv_bfloat16* o1ts = (__nv_bfloat16*)p;

    cudaFuncSetAttribute(gemm_mma<0>, cudaFuncAttributeMaxDynamicSharedMemorySize, SMEM_SZ);
    cudaFuncSetAttribute(gemm_mma<1>, cudaFuncAttributeMaxDynamicSharedMemorySize, SMEM_SZ);

    const int nsplit = (int)(((size_t)B_ * LQ_ * D_ / 4) / 256);   // 32768 blocks

    // 0a) Q split (A-role), K split (B-role)
    split_rows<0><<<nsplit, 256>>>(q,  qs, D_);
    split_rows<1><<<nsplit, 256>>>(kk, ks, D_);
    // 0b) V^T split (B-role): in [S,D] -> out [D,3S]
    tsplit<1><<<dim3(S_ / 32, D_ / 32, B_), 256>>>(v, vts, S_, D_);

    // 1) scores = Q @ K^T / 32 -> aw (fp32)
    gemm_mma<0><<<dim3(S_ / 128, LQ_ / 128, B_), 256, SMEM_SZ>>>(
        qs, ks, aw, nullptr, K3QK, S_,
        (size_t)LQ_ * K3QK, (size_t)S_ * K3QK, (size_t)LQ_ * S_, 0.03125f);

    // 2) masked softmax in place + aw split (A-role)
    softmax_mask_split<<<B_ * LQ_, 256>>>(aw, mask, aws);

    // 2b) aw^T split (A-role): in [LQ,S] -> out [S,3LQ]
    tsplit<0><<<dim3(LQ_ / 32, S_ / 32, B_), 256>>>(aw, awts, LQ_, S_);

    // 3) out1 = aw @ V  ->  o1ts (bf16 split-transposed, B-role)
    gemm_mma<1><<<dim3(D_ / 128, LQ_ / 128, B_), 256, SMEM_SZ>>>(
        aws, vts, nullptr, o1ts, K3A, 0,
        (size_t)LQ_ * K3A, (size_t)D_ * K3A, (size_t)D_ * K3A, 1.0f);

    // 4) output = aw^T @ out1 -> out (fp32)
    gemm_mma<0><<<dim3(D_ / 128, S_ / 128, B_), 256, SMEM_SZ>>>(
        awts, o1ts, out, nullptr, K3A, D_,
        (size_t)S_ * K3A, (size_t)D_ * K3A, (size_t)S_ * D_, 1.0f);
}